// round 5
// baseline (speedup 1.0000x reference)
#include <cuda_runtime.h>
#include <cuda_bf16.h>

#define N_NODES   100000
#define N_EDGES   1200000
#define NUM_GRAPHS 128
#define IN_DIM    5
#define HIDDEN    64
#define CAP       128          // bucket capacity; P(deg>=128)~1e-60 for Poisson(12)

// -------- scratch (device globals; zero at module load; every replay
//          restores the state it found) --------
__device__ __align__(16) float g_h1   [N_NODES * HIDDEN];   // 25.6 MB
__device__ __align__(16) float g_pool [NUM_GRAPHS * HIDDEN]; // zeroed by k_head post-read
__device__ int   g_deg  [N_NODES];                           // counters; zeroed by k_layer2 post-read
__device__ int   g_slots[N_NODES * CAP];                     // 51.2 MB bucket CSR

// ---- f32x2 packed-FMA helpers (sm_103a FFMA2; full fp32 precision) ----
__device__ __forceinline__ void fma2(unsigned long long& d,
                                     unsigned long long a,
                                     unsigned long long b) {
    asm("fma.rn.f32x2 %0, %1, %2, %0;" : "+l"(d) : "l"(a), "l"(b));
}
__device__ __forceinline__ unsigned long long bcast2(float v) {
    unsigned long long r;
    asm("mov.b64 %0, {%1, %1};" : "=l"(r) : "f"(v));
    return r;
}
__device__ __forceinline__ void unpack2(float& lo, float& hi, unsigned long long v) {
    asm("mov.b64 {%0, %1}, %2;" : "=f"(lo), "=f"(hi) : "l"(v));
}

// -------- K1: bucket fill (count+scan+fill in one pass) --------
__global__ void k_fill(const int* __restrict__ src, const int* __restrict__ dst) {
    int e4 = blockIdx.x * blockDim.x + threadIdx.x;
    if (e4 >= N_EDGES / 4) return;
    int4 s = reinterpret_cast<const int4*>(src)[e4];
    int4 d = reinterpret_cast<const int4*>(dst)[e4];
    int p;
    p = atomicAdd(&g_deg[d.x], 1); if (p < CAP) g_slots[d.x * CAP + p] = s.x;
    p = atomicAdd(&g_deg[d.y], 1); if (p < CAP) g_slots[d.y * CAP + p] = s.y;
    p = atomicAdd(&g_deg[d.z], 1); if (p < CAP) g_slots[d.z * CAP + p] = s.z;
    p = atomicAdd(&g_deg[d.w], 1); if (p < CAP) g_slots[d.w * CAP + p] = s.w;
}

// -------- K2: fused layer-1: gather x[src] (4 lanes/node) + GraphConv --------
__global__ __launch_bounds__(256)
void k_layer1(const float* __restrict__ x,
              const float* __restrict__ w_rel,   // [5,64]
              const float* __restrict__ b_rel,
              const float* __restrict__ w_root)  // [5,64]
{
    __shared__ float swr[IN_DIM * HIDDEN];
    __shared__ float swo[IN_DIM * HIDDEN];
    __shared__ float sb[HIDDEN];
    __shared__ float sagg[64][IN_DIM];
    __shared__ float sx  [64][IN_DIM];

    const int t = threadIdx.x;
    const int base = blockIdx.x * 64;

    for (int i = t; i < IN_DIM * HIDDEN; i += 256) { swr[i] = w_rel[i]; swo[i] = w_root[i]; }
    if (t < HIDDEN) sb[t] = b_rel[t];

    // Phase A: 4 lanes per node
    {
        const int nl = t >> 2, l = t & 3;
        const int n = base + nl;
        float a0=0,a1=0,a2=0,a3=0,a4=0;
        if (n < N_NODES) {
            int deg = min(g_deg[n], CAP);
            const int* row = g_slots + n * CAP;
            for (int i = l; i < deg; i += 4) {
                const float* sr = x + (long long)row[i] * IN_DIM;
                a0 += sr[0]; a1 += sr[1]; a2 += sr[2]; a3 += sr[3]; a4 += sr[4];
            }
        }
        #pragma unroll
        for (int off = 1; off <= 2; off <<= 1) {
            a0 += __shfl_xor_sync(0xFFFFFFFFu, a0, off);
            a1 += __shfl_xor_sync(0xFFFFFFFFu, a1, off);
            a2 += __shfl_xor_sync(0xFFFFFFFFu, a2, off);
            a3 += __shfl_xor_sync(0xFFFFFFFFu, a3, off);
            a4 += __shfl_xor_sync(0xFFFFFFFFu, a4, off);
        }
        if (l == 0 && n < N_NODES) {
            sagg[nl][0]=a0; sagg[nl][1]=a1; sagg[nl][2]=a2; sagg[nl][3]=a3; sagg[nl][4]=a4;
            const float* xr = x + (long long)n * IN_DIM;
            sx[nl][0]=xr[0]; sx[nl][1]=xr[1]; sx[nl][2]=xr[2]; sx[nl][3]=xr[3]; sx[nl][4]=xr[4];
        }
    }
    __syncthreads();

    // Phase B: 64x64 outputs over 16 iterations
    #pragma unroll 4
    for (int it = 0; it < 16; it++) {
        int idx = it * 256 + t;
        int nl = idx >> 6, j = idx & 63;
        int node = base + nl;
        if (node >= N_NODES) break;
        float acc = sb[j];
        #pragma unroll
        for (int k = 0; k < IN_DIM; k++)
            acc += sagg[nl][k] * swr[k * HIDDEN + j] + sx[nl][k] * swo[k * HIDDEN + j];
        g_h1[(long long)node * HIDDEN + j] = fmaxf(acc, 0.f);
    }
}

// -------- K3: fused layer-2: gather h1 + GraphConv (FFMA2 GEMM) + pooling --------
#define TM 64
#define SA_STRIDE 68
#define SA_FLOATS (64 * SA_STRIDE)
#define SB_FLOATS (64 * HIDDEN)

__global__ __launch_bounds__(256, 4)
void k_layer2(const int* __restrict__ batch,
              const float* __restrict__ w_rel,   // [64,64]
              const float* __restrict__ b_rel,
              const float* __restrict__ w_root)  // [64,64]
{
    __shared__ __align__(16) float sA[SA_FLOATS];
    __shared__ __align__(16) float sB[SB_FLOATS];
    __shared__ float sbias[HIDDEN];
    __shared__ int   sbatch[TM];

    const int t    = threadIdx.x;
    const int lane = t & 31, wid = t >> 5;
    const int half = lane >> 4, li = lane & 15;
    const int tx   = t & 7;          // col-oct (8 cols)
    const int ty   = t >> 3;         // node-pair (2 nodes)
    const int base = blockIdx.x * TM;
    const int mmax = min(TM, N_NODES - base);

    if (t < HIDDEN) sbias[t] = b_rel[t];
    if (t < TM) sbatch[t] = (base + t < N_NODES) ? batch[base + t] : -1;

    #pragma unroll
    for (int r = 0; r < 16; r++) sB[r * 256 + t] = w_rel[r * 256 + t];

    // Phase A: warp-per-node gather into sA (transposed)
    #pragma unroll 1
    for (int p = 0; p < 8; p++) {
        int m = p * 8 + wid;
        int n = base + m;
        float a0=0,a1=0,a2=0,a3=0;
        if (n < N_NODES) {
            int deg = min(g_deg[n], CAP);
            const int* row = g_slots + n * CAP;
            for (int i = half; i < deg; i += 2) {
                int s = row[i];
                float4 v = *reinterpret_cast<const float4*>(&g_h1[(long long)s * HIDDEN + li * 4]);
                a0 += v.x; a1 += v.y; a2 += v.z; a3 += v.w;
            }
        }
        a0 += __shfl_down_sync(0xFFFFFFFFu, a0, 16);
        a1 += __shfl_down_sync(0xFFFFFFFFu, a1, 16);
        a2 += __shfl_down_sync(0xFFFFFFFFu, a2, 16);
        a3 += __shfl_down_sync(0xFFFFFFFFu, a3, 16);
        if (half == 0) {
            int k = li * 4;
            sA[(k+0) * SA_STRIDE + m] = a0;
            sA[(k+1) * SA_STRIDE + m] = a1;
            sA[(k+2) * SA_STRIDE + m] = a2;
            sA[(k+3) * SA_STRIDE + m] = a3;
        }
    }
    __syncthreads();

    // zero deg counters for the next replay (each node owned by exactly this block)
    if (t < mmax) g_deg[base + t] = 0;

    // acc[i][cp] = packed pair {C[m][2cp], C[m][2cp+1]} for node m = ty*2+i
    unsigned long long acc[2][4];
    #pragma unroll
    for (int i = 0; i < 2; i++)
        #pragma unroll
        for (int c = 0; c < 4; c++) acc[i][c] = 0ull;

    // GEMM stage 0: agg @ W_rel (FFMA2)
    #pragma unroll 8
    for (int k = 0; k < 64; k++) {
        float2 a = *reinterpret_cast<const float2*>(&sA[k * SA_STRIDE + ty * 2]);
        ulonglong2 b0 = *reinterpret_cast<const ulonglong2*>(&sB[k * HIDDEN + tx * 8]);
        ulonglong2 b1 = *reinterpret_cast<const ulonglong2*>(&sB[k * HIDDEN + tx * 8 + 4]);
        unsigned long long a0 = bcast2(a.x), a1 = bcast2(a.y);
        fma2(acc[0][0], a0, b0.x); fma2(acc[0][1], a0, b0.y);
        fma2(acc[0][2], a0, b1.x); fma2(acc[0][3], a0, b1.y);
        fma2(acc[1][0], a1, b0.x); fma2(acc[1][1], a1, b0.y);
        fma2(acc[1][2], a1, b1.x); fma2(acc[1][3], a1, b1.y);
    }
    __syncthreads();

    // reload: sA = h1 tile (transposed), sB = W_root
    #pragma unroll
    for (int r = 0; r < 16; r++) {
        int idx = r * 256 + t;
        int m = idx >> 6, k = idx & 63;
        int node = base + m;
        sA[k * SA_STRIDE + m] = (node < N_NODES) ? g_h1[(long long)node * HIDDEN + k] : 0.f;
        sB[idx] = w_root[idx];
    }
    __syncthreads();

    // GEMM stage 1: h1 @ W_root (FFMA2)
    #pragma unroll 8
    for (int k = 0; k < 64; k++) {
        float2 a = *reinterpret_cast<const float2*>(&sA[k * SA_STRIDE + ty * 2]);
        ulonglong2 b0 = *reinterpret_cast<const ulonglong2*>(&sB[k * HIDDEN + tx * 8]);
        ulonglong2 b1 = *reinterpret_cast<const ulonglong2*>(&sB[k * HIDDEN + tx * 8 + 4]);
        unsigned long long a0 = bcast2(a.x), a1 = bcast2(a.y);
        fma2(acc[0][0], a0, b0.x); fma2(acc[0][1], a0, b0.y);
        fma2(acc[0][2], a0, b1.x); fma2(acc[0][3], a0, b1.y);
        fma2(acc[1][0], a1, b0.x); fma2(acc[1][1], a1, b0.y);
        fma2(acc[1][2], a1, b1.x); fma2(acc[1][3], a1, b1.y);
    }
    __syncthreads();

    // bias + relu, stage C tile in sB: rows m = ty*2+i, cols tx*8 + 2cp + {0,1}
    #pragma unroll
    for (int i = 0; i < 2; i++) {
        int m = ty * 2 + i;
        #pragma unroll
        for (int c = 0; c < 4; c++) {
            int j = tx * 8 + c * 2;
            float lo, hi;
            unpack2(lo, hi, acc[i][c]);
            float2 v;
            v.x = fmaxf(lo + sbias[j],     0.f);
            v.y = fmaxf(hi + sbias[j + 1], 0.f);
            *reinterpret_cast<float2*>(&sB[m * HIDDEN + j]) = v;
        }
    }
    __syncthreads();

    // Pooling: sorted batch, run-length flush per column
    if (t < HIDDEN) {
        int j = t;
        int gc = sbatch[0];
        float sum = 0.f;
        for (int m = 0; m < mmax; m++) {
            int g = sbatch[m];
            if (g != gc) {
                atomicAdd(&g_pool[gc * HIDDEN + j], sum);
                gc = g; sum = 0.f;
            }
            sum += sB[m * HIDDEN + j];
        }
        atomicAdd(&g_pool[gc * HIDDEN + j], sum);
    }
}

// -------- K4: final MLP head; counts via binary search; zeroes g_pool --------
__global__ void k_head(const int* __restrict__ batch,
                       const float* __restrict__ w_h1,  // [128,64]
                       const float* __restrict__ b_h1,
                       const float* __restrict__ w_h2,  // [64,1]
                       const float* __restrict__ b_h2,
                       float* __restrict__ out)
{
    __shared__ float sw1[2 * HIDDEN * HIDDEN];
    __shared__ float sb1[HIDDEN];
    __shared__ float sw2[HIDDEN];
    int t = threadIdx.x;
    for (int i = t; i < 2 * HIDDEN * HIDDEN; i += blockDim.x) sw1[i] = w_h1[i];
    if (t < HIDDEN) { sb1[t] = b_h1[t]; sw2[t] = w_h2[t]; }
    __syncthreads();

    int g = t;
    if (g >= NUM_GRAPHS) return;

    // node count for graph g: lower_bound(g+1) - lower_bound(g) on sorted batch
    int cnt;
    {
        int lo = 0, hi = N_NODES;
        while (lo < hi) { int mid = (lo + hi) >> 1; if (batch[mid] < g) lo = mid + 1; else hi = mid; }
        int lb0 = lo;
        lo = 0; hi = N_NODES;
        while (lo < hi) { int mid = (lo + hi) >> 1; if (batch[mid] < g + 1) lo = mid + 1; else hi = mid; }
        cnt = lo - lb0;
    }
    float inv = 1.f / fmaxf((float)cnt, 1.f);

    float h[HIDDEN];
    #pragma unroll
    for (int j = 0; j < HIDDEN; j++) h[j] = sb1[j];

    for (int i = 0; i < HIDDEN; i++) {
        float p = g_pool[g * HIDDEN + i];
        float gm = p * inv;
        #pragma unroll 8
        for (int j = 0; j < HIDDEN; j++)
            h[j] += gm * sw1[i * HIDDEN + j] + p * sw1[(HIDDEN + i) * HIDDEN + j];
    }
    float o = b_h2[0];
    #pragma unroll
    for (int j = 0; j < HIDDEN; j++) o += fmaxf(h[j], 0.f) * sw2[j];
    out[g] = o;

    // leave pool zeroed for the next replay
    #pragma unroll
    for (int i = 0; i < HIDDEN; i++) g_pool[g * HIDDEN + i] = 0.f;
}

extern "C" void kernel_launch(void* const* d_in, const int* in_sizes, int n_in,
                              void* d_out, int out_size) {
    const float* x       = (const float*)d_in[0];
    const int*   eidx    = (const int*)d_in[1];
    const int*   batch   = (const int*)d_in[2];
    const float* w_rel1  = (const float*)d_in[3];
    const float* b_rel1  = (const float*)d_in[4];
    const float* w_root1 = (const float*)d_in[5];
    const float* w_rel2  = (const float*)d_in[6];
    const float* b_rel2  = (const float*)d_in[7];
    const float* w_root2 = (const float*)d_in[8];
    const float* w_h1    = (const float*)d_in[9];
    const float* b_h1    = (const float*)d_in[10];
    const float* w_h2    = (const float*)d_in[11];
    const float* b_h2    = (const float*)d_in[12];
    float* out = (float*)d_out;

    const int* src = eidx;
    const int* dst = eidx + N_EDGES;

    k_fill  <<<(N_EDGES / 4 + 255) / 256, 256>>>(src, dst);
    k_layer1<<<(N_NODES + 63) / 64, 256>>>(x, w_rel1, b_rel1, w_root1);
    k_layer2<<<(N_NODES + TM - 1) / TM, 256>>>(batch, w_rel2, b_rel2, w_root2);
    k_head  <<<1, 128>>>(batch, w_h1, b_h1, w_h2, b_h2, out);
}

// round 6
// speedup vs baseline: 1.6048x; 1.6048x over previous
#include <cuda_runtime.h>
#include <cuda_bf16.h>

#define N_NODES   100000
#define N_EDGES   1200000
#define NUM_GRAPHS 128
#define IN_DIM    5
#define HIDDEN    64
#define CAP       128          // bucket capacity; P(deg>=128)~1e-60 for Poisson(12)

// -------- scratch (device globals; zero at module load; every replay
//          restores the state it found) --------
__device__ __align__(16) float g_h1   [N_NODES * HIDDEN];   // 25.6 MB
__device__ __align__(16) float g_pool [NUM_GRAPHS * HIDDEN]; // zeroed by k_head post-read
__device__ int   g_deg  [N_NODES];                           // counters; zeroed by k_layer2 post-read
__device__ int   g_slots[N_NODES * CAP];                     // 51.2 MB bucket CSR

// ---- f32x2 packed-FMA helpers (sm_103a FFMA2; full fp32 precision) ----
__device__ __forceinline__ void fma2(unsigned long long& d,
                                     unsigned long long a,
                                     unsigned long long b) {
    asm("fma.rn.f32x2 %0, %1, %2, %0;" : "+l"(d) : "l"(a), "l"(b));
}
__device__ __forceinline__ unsigned long long bcast2(float v) {
    unsigned long long r;
    asm("mov.b64 %0, {%1, %1};" : "=l"(r) : "f"(v));
    return r;
}
__device__ __forceinline__ void unpack2(float& lo, float& hi, unsigned long long v) {
    asm("mov.b64 {%0, %1}, %2;" : "=f"(lo), "=f"(hi) : "l"(v));
}

// -------- K1: bucket fill (count+scan+fill in one pass) --------
__global__ void k_fill(const int* __restrict__ src, const int* __restrict__ dst) {
    int e4 = blockIdx.x * blockDim.x + threadIdx.x;
    if (e4 >= N_EDGES / 4) return;
    int4 s = reinterpret_cast<const int4*>(src)[e4];
    int4 d = reinterpret_cast<const int4*>(dst)[e4];
    int p;
    p = atomicAdd(&g_deg[d.x], 1); if (p < CAP) g_slots[d.x * CAP + p] = s.x;
    p = atomicAdd(&g_deg[d.y], 1); if (p < CAP) g_slots[d.y * CAP + p] = s.y;
    p = atomicAdd(&g_deg[d.z], 1); if (p < CAP) g_slots[d.z * CAP + p] = s.z;
    p = atomicAdd(&g_deg[d.w], 1); if (p < CAP) g_slots[d.w * CAP + p] = s.w;
}

// -------- K2: fused layer-1: gather x[src] (4 lanes/node) + GraphConv --------
__global__ __launch_bounds__(256)
void k_layer1(const float* __restrict__ x,
              const float* __restrict__ w_rel,   // [5,64]
              const float* __restrict__ b_rel,
              const float* __restrict__ w_root)  // [5,64]
{
    __shared__ float swr[IN_DIM * HIDDEN];
    __shared__ float swo[IN_DIM * HIDDEN];
    __shared__ float sb[HIDDEN];
    __shared__ float sagg[64][IN_DIM];
    __shared__ float sx  [64][IN_DIM];

    const int t = threadIdx.x;
    const int base = blockIdx.x * 64;

    for (int i = t; i < IN_DIM * HIDDEN; i += 256) { swr[i] = w_rel[i]; swo[i] = w_root[i]; }
    if (t < HIDDEN) sb[t] = b_rel[t];

    // Phase A: 4 lanes per node
    {
        const int nl = t >> 2, l = t & 3;
        const int n = base + nl;
        float a0=0,a1=0,a2=0,a3=0,a4=0;
        if (n < N_NODES) {
            int deg = min(g_deg[n], CAP);
            const int* row = g_slots + n * CAP;
            for (int i = l; i < deg; i += 4) {
                const float* sr = x + (long long)row[i] * IN_DIM;
                a0 += sr[0]; a1 += sr[1]; a2 += sr[2]; a3 += sr[3]; a4 += sr[4];
            }
        }
        #pragma unroll
        for (int off = 1; off <= 2; off <<= 1) {
            a0 += __shfl_xor_sync(0xFFFFFFFFu, a0, off);
            a1 += __shfl_xor_sync(0xFFFFFFFFu, a1, off);
            a2 += __shfl_xor_sync(0xFFFFFFFFu, a2, off);
            a3 += __shfl_xor_sync(0xFFFFFFFFu, a3, off);
            a4 += __shfl_xor_sync(0xFFFFFFFFu, a4, off);
        }
        if (l == 0 && n < N_NODES) {
            sagg[nl][0]=a0; sagg[nl][1]=a1; sagg[nl][2]=a2; sagg[nl][3]=a3; sagg[nl][4]=a4;
            const float* xr = x + (long long)n * IN_DIM;
            sx[nl][0]=xr[0]; sx[nl][1]=xr[1]; sx[nl][2]=xr[2]; sx[nl][3]=xr[3]; sx[nl][4]=xr[4];
        }
    }
    __syncthreads();

    // Phase B: 64x64 outputs over 16 iterations
    #pragma unroll 4
    for (int it = 0; it < 16; it++) {
        int idx = it * 256 + t;
        int nl = idx >> 6, j = idx & 63;
        int node = base + nl;
        if (node >= N_NODES) break;
        float acc = sb[j];
        #pragma unroll
        for (int k = 0; k < IN_DIM; k++)
            acc += sagg[nl][k] * swr[k * HIDDEN + j] + sx[nl][k] * swo[k * HIDDEN + j];
        g_h1[(long long)node * HIDDEN + j] = fmaxf(acc, 0.f);
    }
}

// -------- K3: fused layer-2: gather h1 + GraphConv (FFMA2 GEMM) + pooling --------
#define TM 64
#define SA_STRIDE 68
#define SA_FLOATS (64 * SA_STRIDE)
#define SB_FLOATS (64 * HIDDEN)

__global__ __launch_bounds__(256, 4)
void k_layer2(const int* __restrict__ batch,
              const float* __restrict__ w_rel,   // [64,64]
              const float* __restrict__ b_rel,
              const float* __restrict__ w_root)  // [64,64]
{
    __shared__ __align__(16) float sA[SA_FLOATS];
    __shared__ __align__(16) float sB[SB_FLOATS];
    __shared__ float sbias[HIDDEN];
    __shared__ int   sbatch[TM];

    const int t    = threadIdx.x;
    const int lane = t & 31, wid = t >> 5;
    const int half = lane >> 4, li = lane & 15;
    const int tx   = t & 7;          // col-oct (8 cols)
    const int ty   = t >> 3;         // node-pair (2 nodes)
    const int base = blockIdx.x * TM;
    const int mmax = min(TM, N_NODES - base);

    if (t < HIDDEN) sbias[t] = b_rel[t];
    if (t < TM) sbatch[t] = (base + t < N_NODES) ? batch[base + t] : -1;

    #pragma unroll
    for (int r = 0; r < 16; r++) sB[r * 256 + t] = w_rel[r * 256 + t];

    // Phase A: warp-per-node gather into sA (transposed)
    #pragma unroll 1
    for (int p = 0; p < 8; p++) {
        int m = p * 8 + wid;
        int n = base + m;
        float a0=0,a1=0,a2=0,a3=0;
        if (n < N_NODES) {
            int deg = min(g_deg[n], CAP);
            const int* row = g_slots + n * CAP;
            for (int i = half; i < deg; i += 2) {
                int s = row[i];
                float4 v = *reinterpret_cast<const float4*>(&g_h1[(long long)s * HIDDEN + li * 4]);
                a0 += v.x; a1 += v.y; a2 += v.z; a3 += v.w;
            }
        }
        a0 += __shfl_down_sync(0xFFFFFFFFu, a0, 16);
        a1 += __shfl_down_sync(0xFFFFFFFFu, a1, 16);
        a2 += __shfl_down_sync(0xFFFFFFFFu, a2, 16);
        a3 += __shfl_down_sync(0xFFFFFFFFu, a3, 16);
        if (half == 0) {
            int k = li * 4;
            sA[(k+0) * SA_STRIDE + m] = a0;
            sA[(k+1) * SA_STRIDE + m] = a1;
            sA[(k+2) * SA_STRIDE + m] = a2;
            sA[(k+3) * SA_STRIDE + m] = a3;
        }
    }
    __syncthreads();

    // zero deg counters for the next replay (each node owned by exactly this block)
    if (t < mmax) g_deg[base + t] = 0;

    // acc[i][cp] = packed pair {C[m][2cp], C[m][2cp+1]} for node m = ty*2+i
    unsigned long long acc[2][4];
    #pragma unroll
    for (int i = 0; i < 2; i++)
        #pragma unroll
        for (int c = 0; c < 4; c++) acc[i][c] = 0ull;

    // GEMM stage 0: agg @ W_rel (FFMA2)
    #pragma unroll 8
    for (int k = 0; k < 64; k++) {
        float2 a = *reinterpret_cast<const float2*>(&sA[k * SA_STRIDE + ty * 2]);
        ulonglong2 b0 = *reinterpret_cast<const ulonglong2*>(&sB[k * HIDDEN + tx * 8]);
        ulonglong2 b1 = *reinterpret_cast<const ulonglong2*>(&sB[k * HIDDEN + tx * 8 + 4]);
        unsigned long long a0 = bcast2(a.x), a1 = bcast2(a.y);
        fma2(acc[0][0], a0, b0.x); fma2(acc[0][1], a0, b0.y);
        fma2(acc[0][2], a0, b1.x); fma2(acc[0][3], a0, b1.y);
        fma2(acc[1][0], a1, b0.x); fma2(acc[1][1], a1, b0.y);
        fma2(acc[1][2], a1, b1.x); fma2(acc[1][3], a1, b1.y);
    }
    __syncthreads();

    // reload: sA = h1 tile (transposed), sB = W_root
    #pragma unroll
    for (int r = 0; r < 16; r++) {
        int idx = r * 256 + t;
        int m = idx >> 6, k = idx & 63;
        int node = base + m;
        sA[k * SA_STRIDE + m] = (node < N_NODES) ? g_h1[(long long)node * HIDDEN + k] : 0.f;
        sB[idx] = w_root[idx];
    }
    __syncthreads();

    // GEMM stage 1: h1 @ W_root (FFMA2)
    #pragma unroll 8
    for (int k = 0; k < 64; k++) {
        float2 a = *reinterpret_cast<const float2*>(&sA[k * SA_STRIDE + ty * 2]);
        ulonglong2 b0 = *reinterpret_cast<const ulonglong2*>(&sB[k * HIDDEN + tx * 8]);
        ulonglong2 b1 = *reinterpret_cast<const ulonglong2*>(&sB[k * HIDDEN + tx * 8 + 4]);
        unsigned long long a0 = bcast2(a.x), a1 = bcast2(a.y);
        fma2(acc[0][0], a0, b0.x); fma2(acc[0][1], a0, b0.y);
        fma2(acc[0][2], a0, b1.x); fma2(acc[0][3], a0, b1.y);
        fma2(acc[1][0], a1, b0.x); fma2(acc[1][1], a1, b0.y);
        fma2(acc[1][2], a1, b1.x); fma2(acc[1][3], a1, b1.y);
    }
    __syncthreads();

    // bias + relu, stage C tile in sB
    #pragma unroll
    for (int i = 0; i < 2; i++) {
        int m = ty * 2 + i;
        #pragma unroll
        for (int c = 0; c < 4; c++) {
            int j = tx * 8 + c * 2;
            float lo, hi;
            unpack2(lo, hi, acc[i][c]);
            float2 v;
            v.x = fmaxf(lo + sbias[j],     0.f);
            v.y = fmaxf(hi + sbias[j + 1], 0.f);
            *reinterpret_cast<float2*>(&sB[m * HIDDEN + j]) = v;
        }
    }
    __syncthreads();

    // Pooling: sorted batch, run-length flush per column
    if (t < HIDDEN) {
        int j = t;
        int gc = sbatch[0];
        float sum = 0.f;
        for (int m = 0; m < mmax; m++) {
            int g = sbatch[m];
            if (g != gc) {
                atomicAdd(&g_pool[gc * HIDDEN + j], sum);
                gc = g; sum = 0.f;
            }
            sum += sB[m * HIDDEN + j];
        }
        atomicAdd(&g_pool[gc * HIDDEN + j], sum);
    }
}

// -------- K4: parallel MLP head: block = graph, thread = hidden unit --------
// No register arrays -> no spills. w_h1 reads are coalesced (consecutive j).
__global__ __launch_bounds__(64)
void k_head(const int* __restrict__ batch,
            const float* __restrict__ w_h1,  // [128,64]
            const float* __restrict__ b_h1,
            const float* __restrict__ w_h2,  // [64,1]
            const float* __restrict__ b_h2,
            float* __restrict__ out)
{
    __shared__ float s_pool[HIDDEN];
    __shared__ float s_red[2];
    __shared__ float s_inv;

    const int g = blockIdx.x;
    const int j = threadIdx.x;

    // stage pool row, then zero it for the next replay
    s_pool[j] = g_pool[g * HIDDEN + j];
    g_pool[g * HIDDEN + j] = 0.f;

    if (j == 0) {
        // node count of graph g: lower_bound(g+1) - lower_bound(g)
        int lo = 0, hi = N_NODES;
        while (lo < hi) { int mid = (lo + hi) >> 1; if (batch[mid] < g) lo = mid + 1; else hi = mid; }
        int lb0 = lo;
        lo = 0; hi = N_NODES;
        while (lo < hi) { int mid = (lo + hi) >> 1; if (batch[mid] < g + 1) lo = mid + 1; else hi = mid; }
        s_inv = 1.f / fmaxf((float)(lo - lb0), 1.f);
    }
    __syncthreads();
    const float inv = s_inv;

    // h_j = b1[j] + sum_i (pool_i*inv) * w1[i][j] + pool_i * w1[64+i][j]
    float acc = b_h1[j];
    #pragma unroll 8
    for (int i = 0; i < HIDDEN; i++) {
        float p = s_pool[i];
        acc += (p * inv) * w_h1[i * HIDDEN + j] + p * w_h1[(HIDDEN + i) * HIDDEN + j];
    }
    float v = fmaxf(acc, 0.f) * w_h2[j];

    // reduce 64 values: warp reduce, then combine 2 warps
    #pragma unroll
    for (int off = 16; off > 0; off >>= 1)
        v += __shfl_down_sync(0xFFFFFFFFu, v, off);
    if ((j & 31) == 0) s_red[j >> 5] = v;
    __syncthreads();
    if (j == 0) out[g] = s_red[0] + s_red[1] + b_h2[0];
}

extern "C" void kernel_launch(void* const* d_in, const int* in_sizes, int n_in,
                              void* d_out, int out_size) {
    const float* x       = (const float*)d_in[0];
    const int*   eidx    = (const int*)d_in[1];
    const int*   batch   = (const int*)d_in[2];
    const float* w_rel1  = (const float*)d_in[3];
    const float* b_rel1  = (const float*)d_in[4];
    const float* w_root1 = (const float*)d_in[5];
    const float* w_rel2  = (const float*)d_in[6];
    const float* b_rel2  = (const float*)d_in[7];
    const float* w_root2 = (const float*)d_in[8];
    const float* w_h1    = (const float*)d_in[9];
    const float* b_h1    = (const float*)d_in[10];
    const float* w_h2    = (const float*)d_in[11];
    const float* b_h2    = (const float*)d_in[12];
    float* out = (float*)d_out;

    const int* src = eidx;
    const int* dst = eidx + N_EDGES;

    k_fill  <<<(N_EDGES / 4 + 255) / 256, 256>>>(src, dst);
    k_layer1<<<(N_NODES + 63) / 64, 256>>>(x, w_rel1, b_rel1, w_root1);
    k_layer2<<<(N_NODES + TM - 1) / TM, 256>>>(batch, w_rel2, b_rel2, w_root2);
    k_head  <<<NUM_GRAPHS, 64>>>(batch, w_h1, b_h1, w_h2, b_h2, out);
}